// round 2
// baseline (speedup 1.0000x reference)
#include <cuda_runtime.h>
#include <cuda_bf16.h>

// Problem constants (fixed shapes from setup_inputs)
#define HH 128
#define WW 128
#define NBATCH 4
#define CYC 21
#define RR 5
#define TILE 16
#define HALO 26            // TILE + 2*RR
#define NCELL (HALO*HALO)  // 676
#define NBLK 256           // 8*8*4

__device__ float g_p1[NBLK];
__device__ float g_p2[NBLK];

__global__ __launch_bounds__(128) void crf_main(const float* __restrict__ x,
                                                const float* __restrict__ y) {
    extern __shared__ float smem_raw[];
    float4* ysh = (float4*)smem_raw;        // [6][676] float4 (channel-last, padded 21->24)
    float4* Ash = ysh + 6 * NCELL;          // [676] float4 : (x0, x1, x2, 0); OOB cells all-zero
    float*  red = (float*)(Ash + NCELL);    // [8] reduction scratch

    const int tid = threadIdx.x;
    const int tx  = tid & 15;       // 0..15  (w within tile)
    const int tyh = tid >> 4;       // 0..7   (handles rows 2*tyh and 2*tyh+1)
    const int bx = blockIdx.x, by = blockIdx.y, n = blockIdx.z;
    const int th0 = by * TILE, tw0 = bx * TILE;

    const float* yb = y + (size_t)n * CYC * HH * WW;
    const float* xb = x + (size_t)n * 3 * HH * WW;

    // ---- Load halo tiles into shared memory ----
    for (int cell = tid; cell < NCELL; cell += 128) {
        int ly = cell / HALO, lx = cell - ly * HALO;
        int gh = th0 - RR + ly, gw = tw0 - RR + lx;
        bool v = ((unsigned)gh < HH) && ((unsigned)gw < WW);
        int gidx = gh * WW + gw;
        float4 a = make_float4(0.f, 0.f, 0.f, 0.f);
        if (v) {
            a.x = xb[gidx];
            a.y = xb[HH * WW + gidx];
            a.z = xb[2 * HH * WW + gidx];
        }
        Ash[cell] = a;
        #pragma unroll
        for (int c4 = 0; c4 < 6; ++c4) {
            float4 t = make_float4(0.f, 0.f, 0.f, 0.f);
            if (v) {
                const int c = 4 * c4;
                t.x = yb[c * HH * WW + gidx];
                if (c + 1 < CYC) t.y = yb[(c + 1) * HH * WW + gidx];
                if (c + 2 < CYC) t.z = yb[(c + 2) * HH * WW + gidx];
                if (c + 3 < CYC) t.w = yb[(c + 3) * HH * WW + gidx];
            }
            ysh[c4 * NCELL + cell] = t;
        }
    }
    __syncthreads();

    // ---- Per-thread: two vertically adjacent center pixels ----
    const int ly0 = 2 * tyh + RR;      // halo row of pixel0 center
    const int lxc = tx + RR;
    float4 yc0[6], yc1[6];
    #pragma unroll
    for (int c4 = 0; c4 < 6; ++c4) {
        yc0[c4] = ysh[c4 * NCELL + ly0 * HALO + lxc];
        yc1[c4] = ysh[c4 * NCELL + (ly0 + 1) * HALO + lxc];
    }
    const float4 xc0 = Ash[ly0 * HALO + lxc];
    const float4 xc1 = Ash[(ly0 + 1) * HALO + lxc];
    const float wf  = (float)(tw0 + tx);
    const float h0f = (float)(th0 + 2 * tyh);
    const float h1f = h0f + 1.0f;
    const float INV6 = 1.0f / 6.0f;

    float acc1 = 0.f, acc2 = 0.f;

    // Union neighbor window: 12 rows x 11 cols serves both center pixels.
    for (int ii = 0; ii < 12; ++ii) {
        const int lyn = 2 * tyh + ii;
        const int gnh = th0 - RR + lyn;
        const bool rowv = (unsigned)gnh < HH;
        #pragma unroll
        for (int dj = 0; dj < 11; ++dj) {
            const int lxn = tx + dj;
            const int gnw = tw0 - RR + lxn;
            const bool valid = rowv && ((unsigned)gnw < WW);
            const int cidx = lyn * HALO + lxn;

            const float4 xv = Ash[cidx];

            float dot0 = 0.f, dot1 = 0.f;
            #pragma unroll
            for (int c4 = 0; c4 < 6; ++c4) {
                const float4 v = ysh[c4 * NCELL + cidx];
                dot0 += v.x * yc0[c4].x + v.y * yc0[c4].y + v.z * yc0[c4].z + v.w * yc0[c4].w;
                dot1 += v.x * yc1[c4].x + v.y * yc1[c4].y + v.z * yc1[c4].z + v.w * yc1[c4].w;
            }

            const float dXv = valid ? (float)(dj - RR) * INV6 : -wf * INV6;

            // pixel0: offset di = ii (valid for ii in [0,10])
            if (ii < 11) {
                const int di = ii;
                const float d0 = xv.x - xc0.x, d1 = xv.y - xc0.y, d2 = xv.z - xc0.z;
                const float s = d0 * d0 + d1 * d1 + d2 * d2;
                const float dY = valid ? (float)(di - RR) * INV6 : -h0f * INV6;
                const float exy = __expf(-0.5f * (dXv * dXv + dY * dY));
                float K = exy * (0.9f * __expf(-50.f * s) + 0.1f);
                if (di == RR && dj == RR) K = 0.f;
                acc1 += K;
                acc2 += K * dot0;
            }
            // pixel1: offset di = ii-1 (valid for ii in [1,11])
            if (ii >= 1) {
                const int di = ii - 1;
                const float d0 = xv.x - xc1.x, d1 = xv.y - xc1.y, d2 = xv.z - xc1.z;
                const float s = d0 * d0 + d1 * d1 + d2 * d2;
                const float dY = valid ? (float)(di - RR) * INV6 : -h1f * INV6;
                const float exy = __expf(-0.5f * (dXv * dXv + dY * dY));
                float K = exy * (0.9f * __expf(-50.f * s) + 0.1f);
                if (di == RR && dj == RR) K = 0.f;
                acc1 += K;
                acc2 += K * dot1;
            }
        }
    }

    // ---- Block reduction (deterministic) ----
    #pragma unroll
    for (int o = 16; o > 0; o >>= 1) {
        acc1 += __shfl_xor_sync(0xffffffffu, acc1, o);
        acc2 += __shfl_xor_sync(0xffffffffu, acc2, o);
    }
    const int warp = tid >> 5, lane = tid & 31;
    if (lane == 0) { red[warp] = acc1; red[4 + warp] = acc2; }
    __syncthreads();
    if (tid == 0) {
        const float s1 = red[0] + red[1] + red[2] + red[3];
        const float s2 = red[4] + red[5] + red[6] + red[7];
        const int bidx = (n * 8 + by) * 8 + bx;
        g_p1[bidx] = s1;
        g_p2[bidx] = s2;
    }
}

__global__ void crf_final(float* __restrict__ out) {
    __shared__ float s1sh[NBLK];
    __shared__ float s2sh[NBLK];
    const int t = threadIdx.x;
    s1sh[t] = g_p1[t];
    s2sh[t] = g_p2[t];
    __syncthreads();
    #pragma unroll
    for (int s = NBLK / 2; s > 0; s >>= 1) {
        if (t < s) { s1sh[t] += s1sh[t + s]; s2sh[t] += s2sh[t + s]; }
        __syncthreads();
    }
    if (t == 0) {
        out[0] = (s1sh[0] - s2sh[0]) * (1.0f / 65536.0f);
    }
}

extern "C" void kernel_launch(void* const* d_in, const int* in_sizes, int n_in,
                              void* d_out, int out_size) {
    const float* x = (const float*)d_in[0];
    const float* y = (const float*)d_in[1];
    (void)in_sizes; (void)n_in; (void)out_size;

    const size_t smem = (size_t)(7 * NCELL) * sizeof(float4) + 8 * sizeof(float);
    cudaFuncSetAttribute(crf_main, cudaFuncAttributeMaxDynamicSharedMemorySize, (int)smem);

    dim3 grid(8, 8, NBATCH);
    crf_main<<<grid, 128, smem>>>(x, y);
    crf_final<<<1, NBLK>>>((float*)d_out);
}

// round 3
// speedup vs baseline: 1.2796x; 1.2796x over previous
#include <cuda_runtime.h>
#include <cuda_bf16.h>

#define HH 128
#define WW 128
#define PLANE (HH*WW)
#define CYC 21
#define TW 32
#define TH 16
#define HLW 42
#define HLH 26
#define NC (HLW*HLH)        // 1092 halo cells
#define NT 128
#define NBLK 128            // 4*8*4 blocks

typedef unsigned long long u64;

__device__ float g_part[NBLK];
__device__ unsigned int g_cnt = 0;

__device__ __forceinline__ u64 pack2(float lo, float hi) {
    u64 r; asm("mov.b64 %0,{%1,%2};" : "=l"(r) : "f"(lo), "f"(hi)); return r;
}
__device__ __forceinline__ void unpack2(u64 v, float& lo, float& hi) {
    asm("mov.b64 {%0,%1},%2;" : "=f"(lo), "=f"(hi) : "l"(v));
}
__device__ __forceinline__ u64 add2(u64 a, u64 b) {
    u64 d; asm("add.rn.f32x2 %0,%1,%2;" : "=l"(d) : "l"(a), "l"(b)); return d;
}
__device__ __forceinline__ u64 mul2(u64 a, u64 b) {
    u64 d; asm("mul.rn.f32x2 %0,%1,%2;" : "=l"(d) : "l"(a), "l"(b)); return d;
}
__device__ __forceinline__ u64 ffma2(u64 a, u64 b, u64 c) {
    u64 d; asm("fma.rn.f32x2 %0,%1,%2,%3;" : "=l"(d) : "l"(a), "l"(b), "l"(c)); return d;
}
__device__ __forceinline__ float ex2(float v) {
    float r; asm("ex2.approx.ftz.f32 %0,%1;" : "=f"(r) : "f"(v)); return r;
}

#define CEXP  (-72.13475204444817f)   // -50 * log2(e)
#define CXY   (-0.020037431123458f)   // -log2(e)/72

// column parity swizzle: even cols -> [0,21), odd cols -> [21,42)
__device__ __forceinline__ int swz(int c) { return (c & 1) * 21 + (c >> 1); }

__global__ __launch_bounds__(NT, 1) void crf_fused(const float* __restrict__ x,
                                                   const float* __restrict__ y,
                                                   float* __restrict__ out) {
    extern __shared__ float4 smem4[];
    float4* ysh4 = smem4;                 // [6][NC] float4 (y channels packed 21->24, padded 0)
    float4* Ash4 = smem4 + 6 * NC;        // [NC] (x0,x1,x2,0); OOB cells all-zero
    const ulonglong2* ysh2 = (const ulonglong2*)ysh4;
    __shared__ float TAB[169];            // 13x13: exy at [di+1][dj+1], zero border & center
    __shared__ float red[4];
    __shared__ int lastflag;

    const int tid = threadIdx.x;
    const int tx = tid & 15, ty = tid >> 4;
    const int th0 = blockIdx.y * TH, tw0 = blockIdx.x * TW;
    const int bz = blockIdx.z;
    const float* xb = x + (size_t)bz * 3 * PLANE;
    const float* yb = y + (size_t)bz * CYC * PLANE;

    // ---- exy table ----
    for (int t = tid; t < 169; t += NT) {
        int r = t / 13 - 1, c = t % 13 - 1;
        float v = 0.0f;
        if ((unsigned)r <= 10u && (unsigned)c <= 10u && !(r == 5 && c == 5))
            v = __expf(-(float)((r - 5) * (r - 5) + (c - 5) * (c - 5)) * (1.0f / 72.0f));
        TAB[t] = v;
    }

    // ---- load halo (parity-swizzled columns), OOB cells = 0 ----
    for (int cell = tid; cell < NC; cell += NT) {
        int r = cell / HLW, c = cell - r * HLW;
        int gh = th0 - 5 + r, gw = tw0 - 5 + c;
        bool v = ((unsigned)gh < HH) && ((unsigned)gw < WW);
        int gidx = gh * WW + gw;
        int dst = r * HLW + swz(c);
        float4 a = make_float4(0.f, 0.f, 0.f, 0.f);
        if (v) { a.x = xb[gidx]; a.y = xb[PLANE + gidx]; a.z = xb[2 * PLANE + gidx]; }
        Ash4[dst] = a;
        #pragma unroll
        for (int c4 = 0; c4 < 6; ++c4) {
            float4 t = make_float4(0.f, 0.f, 0.f, 0.f);
            if (v) {
                int ch = 4 * c4;
                t.x = yb[ch * PLANE + gidx];
                if (ch + 1 < CYC) t.y = yb[(ch + 1) * PLANE + gidx];
                if (ch + 2 < CYC) t.z = yb[(ch + 2) * PLANE + gidx];
                if (ch + 3 < CYC) t.w = yb[(ch + 3) * PLANE + gidx];
            }
            ysh4[c4 * NC + dst] = t;
        }
    }
    __syncthreads();

    // ---- per-thread: 2x2 pixels at (th0+2ty+pr, tw0+2tx+pc) ----
    // negated image centers, packed over the horizontal pixel pair (pc0,pc1)
    u64 ng[2][3];
    #pragma unroll
    for (int pr = 0; pr < 2; ++pr) {
        int ca = (2 * ty + 5 + pr) * HLW;
        float4 x0 = Ash4[ca + swz(2 * tx + 5)];
        float4 x1 = Ash4[ca + swz(2 * tx + 6)];
        ng[pr][0] = pack2(-x0.x, -x1.x);
        ng[pr][1] = pack2(-x0.y, -x1.y);
        ng[pr][2] = pack2(-x0.z, -x1.z);
    }
    float cm[12];
    #pragma unroll
    for (int jj = 0; jj < 12; ++jj)
        cm[jj] = ((unsigned)(tw0 - 5 + 2 * tx + jj) < (unsigned)WW) ? 1.0f : 0.0f;

    u64 S[2][2][12];
    #pragma unroll
    for (int p = 0; p < 4; ++p)
        #pragma unroll
        for (int k = 0; k < 12; ++k) S[p >> 1][p & 1][k] = 0ull;
    float acc1 = 0.0f;
    const int gh0 = th0 - 5 + 2 * ty;

    #pragma unroll 1
    for (int ii = 0; ii < 12; ++ii) {
        const float rm = ((unsigned)(gh0 + ii) < (unsigned)HH) ? 1.0f : 0.0f;
        const int base = (2 * ty + ii) * HLW + tx;
        const float* t1 = TAB + ii * 13;      // pr=1 row
        const float* t0 = t1 + 13;            // pr=0 row
        #pragma unroll
        for (int jj = 0; jj < 12; ++jj) {
            const int cell = base + (jj & 1) * 21 + (jj >> 1);
            const float vm = rm * cm[jj];
            const float4 xv = Ash4[cell];
            u64 yv[12];
            #pragma unroll
            for (int c4 = 0; c4 < 6; ++c4) {
                ulonglong2 q = ysh2[c4 * NC + cell];
                yv[2 * c4] = q.x; yv[2 * c4 + 1] = q.y;
            }
            // image-diff sum of squares, packed over (pc0,pc1), per pr
            const u64 xp0 = pack2(xv.x, xv.x), xp1 = pack2(xv.y, xv.y), xp2 = pack2(xv.z, xv.z);
            float s00, s01, s10, s11;
            {
                u64 d0 = add2(xp0, ng[0][0]), d1 = add2(xp1, ng[0][1]), d2 = add2(xp2, ng[0][2]);
                u64 sp = mul2(d0, d0); sp = ffma2(d1, d1, sp); sp = ffma2(d2, d2, sp);
                unpack2(sp, s00, s01);
            }
            {
                u64 d0 = add2(xp0, ng[1][0]), d1 = add2(xp1, ng[1][1]), d2 = add2(xp2, ng[1][2]);
                u64 sp = mul2(d0, d0); sp = ffma2(d1, d1, sp); sp = ffma2(d2, d2, sp);
                unpack2(sp, s10, s11);
            }
            const float K00 = fmaf(0.9f, ex2(s00 * CEXP), 0.1f) * t0[jj + 1];
            const float K01 = fmaf(0.9f, ex2(s01 * CEXP), 0.1f) * t0[jj];
            const float K10 = fmaf(0.9f, ex2(s10 * CEXP), 0.1f) * t1[jj + 1];
            const float K11 = fmaf(0.9f, ex2(s11 * CEXP), 0.1f) * t1[jj];
            acc1 = fmaf(vm, (K00 + K01) + (K10 + K11), acc1);
            const u64 Kp00 = pack2(K00, K00), Kp01 = pack2(K01, K01);
            const u64 Kp10 = pack2(K10, K10), Kp11 = pack2(K11, K11);
            #pragma unroll
            for (int k = 0; k < 12; ++k) {
                S[0][0][k] = ffma2(yv[k], Kp00, S[0][0][k]);
                S[0][1][k] = ffma2(yv[k], Kp01, S[0][1][k]);
                S[1][0][k] = ffma2(yv[k], Kp10, S[1][0][k]);
                S[1][1][k] = ffma2(yv[k], Kp11, S[1][1][k]);
            }
        }
    }

    // ---- epilogue: acc2 = <y_center, S>, plus closed-form OOB correction to acc1 ----
    float acc2 = 0.0f;
    #pragma unroll
    for (int pr = 0; pr < 2; ++pr) {
        #pragma unroll
        for (int pc = 0; pc < 2; ++pc) {
            const int cell = (2 * ty + 5 + pr) * HLW + swz(2 * tx + 5 + pc);
            u64 dp = 0ull;
            #pragma unroll
            for (int c4 = 0; c4 < 6; ++c4) {
                ulonglong2 q = ysh2[c4 * NC + cell];
                dp = ffma2(q.x, S[pr][pc][2 * c4], dp);
                dp = ffma2(q.y, S[pr][pc][2 * c4 + 1], dp);
            }
            float lo, hi; unpack2(dp, lo, hi);
            acc2 += lo + hi;

            const int h = th0 + 2 * ty + pr, w = tw0 + 2 * tx + pc;
            const int rv = min(10, 132 - h) - max(0, 5 - h) + 1;
            const int cv = min(10, 132 - w) - max(0, 5 - w) + 1;
            const int noob = 121 - rv * cv;
            if (noob > 0) {
                const float4 xc = Ash4[cell];
                const float sx = xc.x * xc.x + xc.y * xc.y + xc.z * xc.z;
                const float Koob = ex2((float)(h * h + w * w) * CXY) *
                                   fmaf(0.9f, ex2(sx * CEXP), 0.1f);
                acc1 += (float)noob * Koob;
            }
        }
    }

    // ---- block reduction + fused final reduction (deterministic) ----
    float part = acc1 - acc2;
    #pragma unroll
    for (int o = 16; o > 0; o >>= 1) part += __shfl_xor_sync(0xffffffffu, part, o);
    const int warp = tid >> 5, lane = tid & 31;
    if (lane == 0) red[warp] = part;
    __syncthreads();
    const int bid = ((bz * gridDim.y) + blockIdx.y) * gridDim.x + blockIdx.x;
    if (tid == 0) {
        g_part[bid] = (red[0] + red[1]) + (red[2] + red[3]);
        __threadfence();
        unsigned old = atomicAdd(&g_cnt, 1u);
        lastflag = (old == NBLK - 1) ? 1 : 0;
    }
    __syncthreads();
    if (lastflag) {
        float v = g_part[tid];   // NBLK == NT == 128
        #pragma unroll
        for (int o = 16; o > 0; o >>= 1) v += __shfl_xor_sync(0xffffffffu, v, o);
        if (lane == 0) red[warp] = v;
        __syncthreads();
        if (tid == 0) {
            out[0] = ((red[0] + red[1]) + (red[2] + red[3])) * (1.0f / 65536.0f);
            g_cnt = 0;
        }
    }
}

extern "C" void kernel_launch(void* const* d_in, const int* in_sizes, int n_in,
                              void* d_out, int out_size) {
    const float* x = (const float*)d_in[0];
    const float* y = (const float*)d_in[1];
    (void)in_sizes; (void)n_in; (void)out_size;
    const size_t smem = (size_t)7 * NC * sizeof(float4);   // 122,304 B
    cudaFuncSetAttribute(crf_fused, cudaFuncAttributeMaxDynamicSharedMemorySize, (int)smem);
    dim3 grid(WW / TW, HH / TH, 4);
    crf_fused<<<grid, NT, smem>>>(x, y, (float*)d_out);
}

// round 4
// speedup vs baseline: 1.3050x; 1.0199x over previous
#include <cuda_runtime.h>
#include <cuda_bf16.h>

#define HH 128
#define WW 128
#define PLANE (HH*WW)
#define CYC 21
#define TW 32
#define TH 16
#define HLW 42
#define HLH 26
#define NC (HLW*HLH)        // 1092 halo cells
#define NT 256              // 2 row-groups x 128
#define NBLK 128            // 4*8*4 blocks

typedef unsigned long long u64;

__device__ float g_part[NBLK];
__device__ unsigned int g_cnt = 0;

__device__ __forceinline__ u64 pack2(float lo, float hi) {
    u64 r; asm("mov.b64 %0,{%1,%2};" : "=l"(r) : "f"(lo), "f"(hi)); return r;
}
__device__ __forceinline__ void unpack2(u64 v, float& lo, float& hi) {
    asm("mov.b64 {%0,%1},%2;" : "=f"(lo), "=f"(hi) : "l"(v));
}
__device__ __forceinline__ u64 add2(u64 a, u64 b) {
    u64 d; asm("add.rn.f32x2 %0,%1,%2;" : "=l"(d) : "l"(a), "l"(b)); return d;
}
__device__ __forceinline__ u64 mul2(u64 a, u64 b) {
    u64 d; asm("mul.rn.f32x2 %0,%1,%2;" : "=l"(d) : "l"(a), "l"(b)); return d;
}
__device__ __forceinline__ u64 ffma2(u64 a, u64 b, u64 c) {
    u64 d; asm("fma.rn.f32x2 %0,%1,%2,%3;" : "=l"(d) : "l"(a), "l"(b), "l"(c)); return d;
}
__device__ __forceinline__ float ex2(float v) {
    float r; asm("ex2.approx.ftz.f32 %0,%1;" : "=f"(r) : "f"(v)); return r;
}

#define CEXP  (-72.13475204444817f)   // -50 * log2(e)
#define CXY   (-0.020037431123458f)   // -log2(e)/72

// column parity swizzle: even cols -> [0,21), odd cols -> [21,42)
__device__ __forceinline__ int swz(int c) { return (c & 1) * 21 + (c >> 1); }

__global__ __launch_bounds__(NT, 1) void crf_fused(const float* __restrict__ x,
                                                   const float* __restrict__ y,
                                                   float* __restrict__ out) {
    extern __shared__ float4 smem4[];
    float4* ysh4 = smem4;                 // [6][NC] float4 (y channels packed 21->24, padded 0)
    float4* Ash4 = smem4 + 6 * NC;        // [NC] (x0,x1,x2,0); OOB cells all-zero
    const ulonglong2* ysh2 = (const ulonglong2*)ysh4;
    __shared__ float TAB[169];            // 13x13: exy at [di+1][dj+1], zero border & center
    __shared__ float red[8];
    __shared__ int lastflag;

    const int tid = threadIdx.x;
    const int p   = tid & 127;        // pixel-quad id
    const int g   = tid >> 7;         // row-group: 0 or 1
    const int tx = p & 15, ty = p >> 4;
    const int th0 = blockIdx.y * TH, tw0 = blockIdx.x * TW;
    const int bz = blockIdx.z;
    const float* xb = x + (size_t)bz * 3 * PLANE;
    const float* yb = y + (size_t)bz * CYC * PLANE;

    // ---- exy table ----
    for (int t = tid; t < 169; t += NT) {
        int r = t / 13 - 1, c = t % 13 - 1;
        float v = 0.0f;
        if ((unsigned)r <= 10u && (unsigned)c <= 10u && !(r == 5 && c == 5))
            v = __expf(-(float)((r - 5) * (r - 5) + (c - 5) * (c - 5)) * (1.0f / 72.0f));
        TAB[t] = v;
    }

    // ---- load halo (parity-swizzled columns), OOB cells = 0 ----
    for (int cell = tid; cell < NC; cell += NT) {
        int r = cell / HLW, c = cell - r * HLW;
        int gh = th0 - 5 + r, gw = tw0 - 5 + c;
        bool v = ((unsigned)gh < HH) && ((unsigned)gw < WW);
        int gidx = gh * WW + gw;
        int dst = r * HLW + swz(c);
        float4 a = make_float4(0.f, 0.f, 0.f, 0.f);
        if (v) { a.x = xb[gidx]; a.y = xb[PLANE + gidx]; a.z = xb[2 * PLANE + gidx]; }
        Ash4[dst] = a;
        #pragma unroll
        for (int c4 = 0; c4 < 6; ++c4) {
            float4 t = make_float4(0.f, 0.f, 0.f, 0.f);
            if (v) {
                int ch = 4 * c4;
                t.x = yb[ch * PLANE + gidx];
                if (ch + 1 < CYC) t.y = yb[(ch + 1) * PLANE + gidx];
                if (ch + 2 < CYC) t.z = yb[(ch + 2) * PLANE + gidx];
                if (ch + 3 < CYC) t.w = yb[(ch + 3) * PLANE + gidx];
            }
            ysh4[c4 * NC + dst] = t;
        }
    }
    __syncthreads();

    // ---- per-thread: 2x2 pixels at (th0+2ty+pr, tw0+2tx+pc), window rows ii%2==g ----
    u64 ng[2][3];
    #pragma unroll
    for (int pr = 0; pr < 2; ++pr) {
        int ca = (2 * ty + 5 + pr) * HLW;
        float4 x0 = Ash4[ca + swz(2 * tx + 5)];
        float4 x1 = Ash4[ca + swz(2 * tx + 6)];
        ng[pr][0] = pack2(-x0.x, -x1.x);
        ng[pr][1] = pack2(-x0.y, -x1.y);
        ng[pr][2] = pack2(-x0.z, -x1.z);
    }
    float cm[12];
    #pragma unroll
    for (int jj = 0; jj < 12; ++jj)
        cm[jj] = ((unsigned)(tw0 - 5 + 2 * tx + jj) < (unsigned)WW) ? 1.0f : 0.0f;

    u64 S[2][2][12];
    #pragma unroll
    for (int q = 0; q < 4; ++q)
        #pragma unroll
        for (int k = 0; k < 12; ++k) S[q >> 1][q & 1][k] = 0ull;
    float acc1 = 0.0f;
    const int gh0 = th0 - 5 + 2 * ty;

    #pragma unroll 1
    for (int ii = g; ii < 12; ii += 2) {
        const float rm = ((unsigned)(gh0 + ii) < (unsigned)HH) ? 1.0f : 0.0f;
        const int base = (2 * ty + ii) * HLW + tx;
        const float* t1 = TAB + ii * 13;      // pr=1 row
        const float* t0 = t1 + 13;            // pr=0 row
        #pragma unroll
        for (int jj = 0; jj < 12; ++jj) {
            const int cell = base + (jj & 1) * 21 + (jj >> 1);
            const float vm = rm * cm[jj];
            const float4 xv = Ash4[cell];
            u64 yv[12];
            #pragma unroll
            for (int c4 = 0; c4 < 6; ++c4) {
                ulonglong2 q = ysh2[c4 * NC + cell];
                yv[2 * c4] = q.x; yv[2 * c4 + 1] = q.y;
            }
            // image-diff sum of squares, packed over (pc0,pc1), per pr
            const u64 xp0 = pack2(xv.x, xv.x), xp1 = pack2(xv.y, xv.y), xp2 = pack2(xv.z, xv.z);
            float s00, s01, s10, s11;
            {
                u64 d0 = add2(xp0, ng[0][0]), d1 = add2(xp1, ng[0][1]), d2 = add2(xp2, ng[0][2]);
                u64 sp = mul2(d0, d0); sp = ffma2(d1, d1, sp); sp = ffma2(d2, d2, sp);
                unpack2(sp, s00, s01);
            }
            {
                u64 d0 = add2(xp0, ng[1][0]), d1 = add2(xp1, ng[1][1]), d2 = add2(xp2, ng[1][2]);
                u64 sp = mul2(d0, d0); sp = ffma2(d1, d1, sp); sp = ffma2(d2, d2, sp);
                unpack2(sp, s10, s11);
            }
            const float K00 = fmaf(0.9f, ex2(s00 * CEXP), 0.1f) * t0[jj + 1];
            const float K01 = fmaf(0.9f, ex2(s01 * CEXP), 0.1f) * t0[jj];
            const float K10 = fmaf(0.9f, ex2(s10 * CEXP), 0.1f) * t1[jj + 1];
            const float K11 = fmaf(0.9f, ex2(s11 * CEXP), 0.1f) * t1[jj];
            acc1 = fmaf(vm, (K00 + K01) + (K10 + K11), acc1);
            const u64 Kp00 = pack2(K00, K00), Kp01 = pack2(K01, K01);
            const u64 Kp10 = pack2(K10, K10), Kp11 = pack2(K11, K11);
            #pragma unroll
            for (int k = 0; k < 12; ++k) {
                S[0][0][k] = ffma2(yv[k], Kp00, S[0][0][k]);
                S[0][1][k] = ffma2(yv[k], Kp01, S[0][1][k]);
                S[1][0][k] = ffma2(yv[k], Kp10, S[1][0][k]);
                S[1][1][k] = ffma2(yv[k], Kp11, S[1][1][k]);
            }
        }
    }

    // ---- epilogue: acc2 = <y_center, S>; group 0 adds closed-form OOB correction ----
    float acc2 = 0.0f;
    #pragma unroll
    for (int pr = 0; pr < 2; ++pr) {
        #pragma unroll
        for (int pc = 0; pc < 2; ++pc) {
            const int cell = (2 * ty + 5 + pr) * HLW + swz(2 * tx + 5 + pc);
            u64 dp = 0ull;
            #pragma unroll
            for (int c4 = 0; c4 < 6; ++c4) {
                ulonglong2 q = ysh2[c4 * NC + cell];
                dp = ffma2(q.x, S[pr][pc][2 * c4], dp);
                dp = ffma2(q.y, S[pr][pc][2 * c4 + 1], dp);
            }
            float lo, hi; unpack2(dp, lo, hi);
            acc2 += lo + hi;

            if (g == 0) {
                const int h = th0 + 2 * ty + pr, w = tw0 + 2 * tx + pc;
                const int rv = min(10, 132 - h) - max(0, 5 - h) + 1;
                const int cv = min(10, 132 - w) - max(0, 5 - w) + 1;
                const int noob = 121 - rv * cv;
                if (noob > 0) {
                    const float4 xc = Ash4[cell];
                    const float sx = xc.x * xc.x + xc.y * xc.y + xc.z * xc.z;
                    const float Koob = ex2((float)(h * h + w * w) * CXY) *
                                       fmaf(0.9f, ex2(sx * CEXP), 0.1f);
                    acc1 += (float)noob * Koob;
                }
            }
        }
    }

    // ---- block reduction + fused final reduction (deterministic) ----
    float part = acc1 - acc2;
    #pragma unroll
    for (int o = 16; o > 0; o >>= 1) part += __shfl_xor_sync(0xffffffffu, part, o);
    const int warp = tid >> 5, lane = tid & 31;
    if (lane == 0) red[warp] = part;
    __syncthreads();
    const int bid = ((bz * gridDim.y) + blockIdx.y) * gridDim.x + blockIdx.x;
    if (tid == 0) {
        float s = 0.f;
        #pragma unroll
        for (int wi = 0; wi < 8; ++wi) s += red[wi];
        g_part[bid] = s;
        __threadfence();
        unsigned old = atomicAdd(&g_cnt, 1u);
        lastflag = (old == NBLK - 1) ? 1 : 0;
    }
    __syncthreads();
    if (lastflag) {
        float v = (tid < NBLK) ? g_part[tid] : 0.0f;
        #pragma unroll
        for (int o = 16; o > 0; o >>= 1) v += __shfl_xor_sync(0xffffffffu, v, o);
        if (lane == 0) red[warp] = v;
        __syncthreads();
        if (tid == 0) {
            float s = 0.f;
            #pragma unroll
            for (int wi = 0; wi < 4; ++wi) s += red[wi];
            out[0] = s * (1.0f / 65536.0f);
            g_cnt = 0;
        }
    }
}

extern "C" void kernel_launch(void* const* d_in, const int* in_sizes, int n_in,
                              void* d_out, int out_size) {
    const float* x = (const float*)d_in[0];
    const float* y = (const float*)d_in[1];
    (void)in_sizes; (void)n_in; (void)out_size;
    const size_t smem = (size_t)7 * NC * sizeof(float4);   // 122,304 B
    cudaFuncSetAttribute(crf_fused, cudaFuncAttributeMaxDynamicSharedMemorySize, (int)smem);
    dim3 grid(WW / TW, HH / TH, 4);
    crf_fused<<<grid, NT, smem>>>(x, y, (float*)d_out);
}

// round 5
// speedup vs baseline: 1.7196x; 1.3178x over previous
#include <cuda_runtime.h>
#include <cuda_bf16.h>

#define HH 128
#define WW 128
#define PLANE (HH*WW)
#define CYC 21
#define TW 32
#define TH 16
#define HLW 42
#define HLH 21              // rows 0..20 (tile + 5 below; no top halo needed)
#define NC (HLW*HLH)        // 882 halo cells
#define NT 256              // 2 jj-parity groups x 128
#define NBLK 128            // 4*8*4 blocks

typedef unsigned long long u64;

__device__ float g_part[NBLK];
__device__ unsigned int g_cnt = 0;

__device__ __forceinline__ u64 pack2(float lo, float hi) {
    u64 r; asm("mov.b64 %0,{%1,%2};" : "=l"(r) : "f"(lo), "f"(hi)); return r;
}
__device__ __forceinline__ void unpack2(u64 v, float& lo, float& hi) {
    asm("mov.b64 {%0,%1},%2;" : "=f"(lo), "=f"(hi) : "l"(v));
}
__device__ __forceinline__ u64 add2(u64 a, u64 b) {
    u64 d; asm("add.rn.f32x2 %0,%1,%2;" : "=l"(d) : "l"(a), "l"(b)); return d;
}
__device__ __forceinline__ u64 mul2(u64 a, u64 b) {
    u64 d; asm("mul.rn.f32x2 %0,%1,%2;" : "=l"(d) : "l"(a), "l"(b)); return d;
}
__device__ __forceinline__ u64 ffma2(u64 a, u64 b, u64 c) {
    u64 d; asm("fma.rn.f32x2 %0,%1,%2,%3;" : "=l"(d) : "l"(a), "l"(b), "l"(c)); return d;
}
__device__ __forceinline__ float ex2(float v) {
    float r; asm("ex2.approx.ftz.f32 %0,%1;" : "=f"(r) : "f"(v)); return r;
}

#define CEXP  (-72.13475204444817f)   // -50 * log2(e)
#define CXY   (-0.020037431123458f)   // -log2(e)/72

// column parity swizzle: even cols -> [0,21), odd cols -> [21,42)
__device__ __forceinline__ int swz(int c) { return (c & 1) * 21 + (c >> 1); }

__global__ __launch_bounds__(NT, 1) void crf_fused(const float* __restrict__ x,
                                                   const float* __restrict__ y,
                                                   float* __restrict__ out) {
    extern __shared__ float4 smem4[];
    float4* ysh4 = smem4;                 // [6][NC] float4 (y channels packed 21->24, padded 0)
    float4* Ash4 = smem4 + 6 * NC;        // [NC] (x0,x1,x2,0); OOB cells all-zero
    const ulonglong2* ysh2 = (const ulonglong2*)ysh4;
    __shared__ float TAB[104];            // [8][13]: 2*exy at [di+1][dj+6], 0 outside half-window H
    __shared__ float red[8];
    __shared__ int lastflag;

    const int tid = threadIdx.x;
    const int p   = tid & 127;        // pixel-quad id
    const int g   = tid >> 7;         // jj-parity group: 0 or 1
    const int tx = p & 15, ty = p >> 4;
    const int th0 = blockIdx.y * TH, tw0 = blockIdx.x * TW;
    const int bz = blockIdx.z;
    const float* xb = x + (size_t)bz * 3 * PLANE;
    const float* yb = y + (size_t)bz * CYC * PLANE;

    // ---- half-window exy table: row ai -> di = ai-1, col bi -> dj = bi-6 ----
    for (int t = tid; t < 104; t += NT) {
        int di = t / 13 - 1, dj = t % 13 - 6;
        float v = 0.0f;
        if (di >= 0 && di <= 5 && dj >= -5 && dj <= 5 && (di > 0 || dj > 0))
            v = 2.0f * __expf(-(float)(di * di + dj * dj) * (1.0f / 72.0f));
        TAB[t] = v;
    }

    // ---- load halo (rows th0..th0+20, cols tw0-5..tw0+36), OOB cells = 0 ----
    for (int cell = tid; cell < NC; cell += NT) {
        int r = cell / HLW, c = cell - r * HLW;
        int gh = th0 + r, gw = tw0 - 5 + c;
        bool v = (gh < HH) && ((unsigned)gw < WW);
        int gidx = gh * WW + gw;
        int dst = r * HLW + swz(c);
        float4 a = make_float4(0.f, 0.f, 0.f, 0.f);
        if (v) { a.x = xb[gidx]; a.y = xb[PLANE + gidx]; a.z = xb[2 * PLANE + gidx]; }
        Ash4[dst] = a;
        #pragma unroll
        for (int c4 = 0; c4 < 6; ++c4) {
            float4 t = make_float4(0.f, 0.f, 0.f, 0.f);
            if (v) {
                int ch = 4 * c4;
                t.x = yb[ch * PLANE + gidx];
                if (ch + 1 < CYC) t.y = yb[(ch + 1) * PLANE + gidx];
                if (ch + 2 < CYC) t.z = yb[(ch + 2) * PLANE + gidx];
                if (ch + 3 < CYC) t.w = yb[(ch + 3) * PLANE + gidx];
            }
            ysh4[c4 * NC + dst] = t;
        }
    }
    __syncthreads();

    // ---- per-thread: 2x2 pixels at (th0+2ty+pr, tw0+2tx+pc) ----
    // centers: y as 12 packed u64 per pixel; x negated & packed over (pc0,pc1)
    u64 yc[2][2][12];
    u64 ng[2][3];
    #pragma unroll
    for (int pr = 0; pr < 2; ++pr) {
        const int ca = (2 * ty + pr) * HLW;
        #pragma unroll
        for (int pc = 0; pc < 2; ++pc) {
            const int cell = ca + swz(2 * tx + 5 + pc);
            #pragma unroll
            for (int c4 = 0; c4 < 6; ++c4) {
                ulonglong2 q = ysh2[c4 * NC + cell];
                yc[pr][pc][2 * c4] = q.x; yc[pr][pc][2 * c4 + 1] = q.y;
            }
        }
        float4 x0 = Ash4[ca + swz(2 * tx + 5)];
        float4 x1 = Ash4[ca + swz(2 * tx + 6)];
        ng[pr][0] = pack2(-x0.x, -x1.x);
        ng[pr][1] = pack2(-x0.y, -x1.y);
        ng[pr][2] = pack2(-x0.z, -x1.z);
    }
    float cm[12];
    #pragma unroll
    for (int jj = 0; jj < 12; ++jj)
        cm[jj] = ((unsigned)(tw0 - 5 + 2 * tx + jj) < (unsigned)WW) ? 1.0f : 0.0f;

    u64 accP[2][2];
    accP[0][0] = accP[0][1] = accP[1][0] = accP[1][1] = 0ull;
    float acc1 = 0.0f;

    // ---- mainloop: 7 rows x 6 cols (this group's jj parity) ----
    #pragma unroll 1
    for (int ii = 0; ii < 7; ++ii) {
        const float rm = ((th0 + 2 * ty + ii) < HH) ? 1.0f : 0.0f;
        // within a group, column parity is fixed: c = 2(tx+m)+g -> swz = g*21 + tx + m
        const int base = (2 * ty + ii) * HLW + g * 21 + tx;
        const float* t1 = TAB + ii * 13;      // pr=1 row (di = ii-1)
        const float* t0 = t1 + 13;            // pr=0 row (di = ii)
        #pragma unroll
        for (int m = 0; m < 6; ++m) {
            const int jj = g + 2 * m;
            const int cell = base + m;
            const float vm = rm * cm[jj];
            const float4 xv = Ash4[cell];
            u64 yv[12];
            #pragma unroll
            for (int c4 = 0; c4 < 6; ++c4) {
                ulonglong2 q = ysh2[c4 * NC + cell];
                yv[2 * c4] = q.x; yv[2 * c4 + 1] = q.y;
            }
            // image-diff sum of squares, packed over (pc0,pc1), per pr
            const u64 xp0 = pack2(xv.x, xv.x), xp1 = pack2(xv.y, xv.y), xp2 = pack2(xv.z, xv.z);
            float s00, s01, s10, s11;
            {
                u64 d0 = add2(xp0, ng[0][0]), d1 = add2(xp1, ng[0][1]), d2 = add2(xp2, ng[0][2]);
                u64 sp = mul2(d0, d0); sp = ffma2(d1, d1, sp); sp = ffma2(d2, d2, sp);
                unpack2(sp, s00, s01);
            }
            {
                u64 d0 = add2(xp0, ng[1][0]), d1 = add2(xp1, ng[1][1]), d2 = add2(xp2, ng[1][2]);
                u64 sp = mul2(d0, d0); sp = ffma2(d1, d1, sp); sp = ffma2(d2, d2, sp);
                unpack2(sp, s10, s11);
            }
            // K = (0.9*exp(-50 s) + 0.1) * 2*exy  (table holds 2*exy, 0 outside H)
            const float K00 = fmaf(0.9f, ex2(s00 * CEXP), 0.1f) * t0[jj + 1];
            const float K01 = fmaf(0.9f, ex2(s01 * CEXP), 0.1f) * t0[jj];
            const float K10 = fmaf(0.9f, ex2(s10 * CEXP), 0.1f) * t1[jj + 1];
            const float K11 = fmaf(0.9f, ex2(s11 * CEXP), 0.1f) * t1[jj];
            acc1 = fmaf(vm, (K00 + K01) + (K10 + K11), acc1);

            // dots <y_center, y_cell> packed over channel pairs; OOB cells are all-zero
            u64 dp00 = mul2(yv[0], yc[0][0][0]);
            u64 dp01 = mul2(yv[0], yc[0][1][0]);
            u64 dp10 = mul2(yv[0], yc[1][0][0]);
            u64 dp11 = mul2(yv[0], yc[1][1][0]);
            #pragma unroll
            for (int k = 1; k < 12; ++k) {
                dp00 = ffma2(yv[k], yc[0][0][k], dp00);
                dp01 = ffma2(yv[k], yc[0][1][k], dp01);
                dp10 = ffma2(yv[k], yc[1][0][k], dp10);
                dp11 = ffma2(yv[k], yc[1][1][k], dp11);
            }
            accP[0][0] = ffma2(pack2(K00, K00), dp00, accP[0][0]);
            accP[0][1] = ffma2(pack2(K01, K01), dp01, accP[0][1]);
            accP[1][0] = ffma2(pack2(K10, K10), dp10, accP[1][0]);
            accP[1][1] = ffma2(pack2(K11, K11), dp11, accP[1][1]);
        }
    }

    // ---- epilogue: horizontal-add packed acc2; group 0 adds closed-form OOB to acc1 ----
    float acc2 = 0.0f;
    #pragma unroll
    for (int pr = 0; pr < 2; ++pr) {
        #pragma unroll
        for (int pc = 0; pc < 2; ++pc) {
            float lo, hi; unpack2(accP[pr][pc], lo, hi);
            acc2 += lo + hi;
            if (g == 0) {
                const int h = th0 + 2 * ty + pr, w = tw0 + 2 * tx + pc;
                const int rv = min(10, 132 - h) - max(0, 5 - h) + 1;
                const int cv = min(10, 132 - w) - max(0, 5 - w) + 1;
                const int noob = 121 - rv * cv;
                if (noob > 0) {
                    const float4 xc = Ash4[(2 * ty + pr) * HLW + swz(2 * tx + 5 + pc)];
                    const float sx = xc.x * xc.x + xc.y * xc.y + xc.z * xc.z;
                    const float Koob = ex2((float)(h * h + w * w) * CXY) *
                                       fmaf(0.9f, ex2(sx * CEXP), 0.1f);
                    acc1 += (float)noob * Koob;
                }
            }
        }
    }

    // ---- block reduction + fused final reduction (deterministic) ----
    float part = acc1 - acc2;
    #pragma unroll
    for (int o = 16; o > 0; o >>= 1) part += __shfl_xor_sync(0xffffffffu, part, o);
    const int warp = tid >> 5, lane = tid & 31;
    if (lane == 0) red[warp] = part;
    __syncthreads();
    const int bid = ((bz * gridDim.y) + blockIdx.y) * gridDim.x + blockIdx.x;
    if (tid == 0) {
        float s = 0.f;
        #pragma unroll
        for (int wi = 0; wi < 8; ++wi) s += red[wi];
        g_part[bid] = s;
        __threadfence();
        unsigned old = atomicAdd(&g_cnt, 1u);
        lastflag = (old == NBLK - 1) ? 1 : 0;
    }
    __syncthreads();
    if (lastflag) {
        float v = (tid < NBLK) ? g_part[tid] : 0.0f;
        #pragma unroll
        for (int o = 16; o > 0; o >>= 1) v += __shfl_xor_sync(0xffffffffu, v, o);
        if (lane == 0) red[warp] = v;
        __syncthreads();
        if (tid == 0) {
            float s = 0.f;
            #pragma unroll
            for (int wi = 0; wi < 4; ++wi) s += red[wi];
            out[0] = s * (1.0f / 65536.0f);
            g_cnt = 0;
        }
    }
}

extern "C" void kernel_launch(void* const* d_in, const int* in_sizes, int n_in,
                              void* d_out, int out_size) {
    const float* x = (const float*)d_in[0];
    const float* y = (const float*)d_in[1];
    (void)in_sizes; (void)n_in; (void)out_size;
    const size_t smem = (size_t)7 * NC * sizeof(float4);   // 98,784 B
    cudaFuncSetAttribute(crf_fused, cudaFuncAttributeMaxDynamicSharedMemorySize, (int)smem);
    dim3 grid(WW / TW, HH / TH, 4);
    crf_fused<<<grid, NT, smem>>>(x, y, (float*)d_out);
}

// round 6
// speedup vs baseline: 1.7761x; 1.0328x over previous
#include <cuda_runtime.h>
#include <cuda_fp16.h>

#define HH 128
#define WW 128
#define PLANE (HH*WW)
#define CYC 21
#define TW 16
#define TH 16
#define HLW 26              // halo cols: tw0-5 .. tw0+20
#define HLH 21              // halo rows: th0 .. th0+20
#define NC (HLW*HLH)        // 546
#define NT 256              // 128 pixel-pairs x 2 jj-parity groups
#define NBLK 256            // 8*8*4

typedef unsigned long long u64;
typedef unsigned int u32;

__device__ float g_part[NBLK];
__device__ unsigned int g_cnt = 0;

__device__ __forceinline__ u64 pack2(float lo, float hi) {
    u64 r; asm("mov.b64 %0,{%1,%2};" : "=l"(r) : "f"(lo), "f"(hi)); return r;
}
__device__ __forceinline__ void unpack2(u64 v, float& lo, float& hi) {
    asm("mov.b64 {%0,%1},%2;" : "=f"(lo), "=f"(hi) : "l"(v));
}
__device__ __forceinline__ u64 add2(u64 a, u64 b) {
    u64 d; asm("add.rn.f32x2 %0,%1,%2;" : "=l"(d) : "l"(a), "l"(b)); return d;
}
__device__ __forceinline__ u64 mul2(u64 a, u64 b) {
    u64 d; asm("mul.rn.f32x2 %0,%1,%2;" : "=l"(d) : "l"(a), "l"(b)); return d;
}
__device__ __forceinline__ u64 ffma2(u64 a, u64 b, u64 c) {
    u64 d; asm("fma.rn.f32x2 %0,%1,%2,%3;" : "=l"(d) : "l"(a), "l"(b), "l"(c)); return d;
}
__device__ __forceinline__ float ex2(float v) {
    float r; asm("ex2.approx.ftz.f32 %0,%1;" : "=f"(r) : "f"(v)); return r;
}
__device__ __forceinline__ u32 hmul2u(u32 a, u32 b) {
    u32 d; asm("mul.rn.f16x2 %0,%1,%2;" : "=r"(d) : "r"(a), "r"(b)); return d;
}
__device__ __forceinline__ u32 hfma2u(u32 a, u32 b, u32 c) {
    u32 d; asm("fma.rn.f16x2 %0,%1,%2,%3;" : "=r"(d) : "r"(a), "r"(b), "r"(c)); return d;
}
__device__ __forceinline__ u32 splat16(float v) {
    u32 d; asm("cvt.rn.f16x2.f32 %0,%1,%1;" : "=r"(d) : "f"(v)); return d;
}

#define CEXP  (-72.13475204444817f)   // -50 * log2(e)
#define CXY   (-0.020037431123458f)   // -log2(e)/72

// column parity swizzle: even cols -> [0,13), odd cols -> [13,26)
__device__ __forceinline__ int swz(int c) { return (c & 1) * 13 + (c >> 1); }

__global__ __launch_bounds__(NT, 2) void crf_fused(const float* __restrict__ x,
                                                   const float* __restrict__ y,
                                                   float* __restrict__ out) {
    __shared__ float4 Ash4[NC];       // (x0,x1,x2,0) fp32; OOB cells all-zero
    __shared__ uint4  ysh[3 * NC];    // y as fp16 half2 pairs, 24 ch (21 + pad), group cg = ch 8cg..8cg+7
    __shared__ float  TAB[78];        // [6][13]: 2*exy at [di][dj+6]; 0 outside half-window H
    __shared__ float  CS[6];          // CS[c] = sum_{k=1..c} exp(-k^2/72)
    __shared__ float  red[8];
    __shared__ int    lastflag;

    const int tid = threadIdx.x;
    const int g   = tid >> 7;         // jj parity group
    const int pid = tid & 127;
    const int px  = pid & 7;          // pair col: pixels (2px, 2px+1)
    const int py  = pid >> 3;         // pixel row 0..15
    const int th0 = blockIdx.y * TH, tw0 = blockIdx.x * TW;
    const int bz = blockIdx.z;
    const float* xb = x + (size_t)bz * 3 * PLANE;
    const float* yb = y + (size_t)bz * CYC * PLANE;

    // ---- tables ----
    for (int t = tid; t < 78; t += NT) {
        int di = t / 13, dj = t % 13 - 6;
        float v = 0.0f;
        if (dj >= -5 && dj <= 5 && (di >= 1 || dj >= 1))
            v = 2.0f * __expf(-(float)(di * di + dj * dj) * (1.0f / 72.0f));
        TAB[t] = v;
    }
    if (tid < 6) {
        float s = 0.0f;
        for (int k = 1; k <= tid; ++k) s += __expf(-(float)(k * k) * (1.0f / 72.0f));
        CS[tid] = s;    // CS[0] = 0
    }

    // ---- halo load: x fp32, y fp16-packed; OOB cells zero ----
    for (int cell = tid; cell < NC; cell += NT) {
        int r = cell / HLW, c = cell - r * HLW;
        int gh = th0 + r, gw = tw0 - 5 + c;
        bool v = (gh < HH) && ((unsigned)gw < WW);
        int gidx = gh * WW + gw;
        int dst = r * HLW + swz(c);
        float4 a = make_float4(0.f, 0.f, 0.f, 0.f);
        if (v) { a.x = xb[gidx]; a.y = xb[PLANE + gidx]; a.z = xb[2 * PLANE + gidx]; }
        Ash4[dst] = a;
        #pragma unroll
        for (int cg = 0; cg < 3; ++cg) {
            uint4 q = make_uint4(0u, 0u, 0u, 0u);
            if (v) {
                u32 h[4];
                #pragma unroll
                for (int pq = 0; pq < 4; ++pq) {
                    int ch = cg * 8 + pq * 2;
                    float a0 = (ch < CYC) ? yb[ch * PLANE + gidx] : 0.f;
                    float a1 = (ch + 1 < CYC) ? yb[(ch + 1) * PLANE + gidx] : 0.f;
                    __half2 hh = __floats2half2_rn(a0, a1);
                    h[pq] = *(u32*)&hh;
                }
                q.x = h[0]; q.y = h[1]; q.z = h[2]; q.w = h[3];
            }
            ysh[cg * NC + dst] = q;
        }
    }
    __syncthreads();

    // ---- per-thread: pixel pair (py, 2px) & (py, 2px+1) ----
    const int cc0 = py * HLW + swz(2 * px + 5);   // pc0 center halo cell
    const int cc1 = py * HLW + swz(2 * px + 6);   // pc1
    u32 yc0[12], yc1[12];
    {
        uint4 a0 = ysh[cc0], b0 = ysh[NC + cc0], c0 = ysh[2 * NC + cc0];
        yc0[0]=a0.x; yc0[1]=a0.y; yc0[2]=a0.z; yc0[3]=a0.w;
        yc0[4]=b0.x; yc0[5]=b0.y; yc0[6]=b0.z; yc0[7]=b0.w;
        yc0[8]=c0.x; yc0[9]=c0.y; yc0[10]=c0.z; yc0[11]=c0.w;
        uint4 a1 = ysh[cc1], b1 = ysh[NC + cc1], c1 = ysh[2 * NC + cc1];
        yc1[0]=a1.x; yc1[1]=a1.y; yc1[2]=a1.z; yc1[3]=a1.w;
        yc1[4]=b1.x; yc1[5]=b1.y; yc1[6]=b1.z; yc1[7]=b1.w;
        yc1[8]=c1.x; yc1[9]=c1.y; yc1[10]=c1.z; yc1[11]=c1.w;
    }
    const float4 xc0 = Ash4[cc0];
    const float4 xc1 = Ash4[cc1];
    const u64 ng0 = pack2(-xc0.x, -xc1.x);
    const u64 ng1 = pack2(-xc0.y, -xc1.y);
    const u64 ng2 = pack2(-xc0.z, -xc1.z);
    const u64 cexp2 = pack2(CEXP, CEXP);

    u32 accP0 = 0u, accP1 = 0u;   // half2 accumulators of K*dot
    float acc1 = 0.0f;
    const float* tg = TAB + g;    // fold g into base so inner offsets are immediates

    // ---- mainloop: 6 rows (di=0..5) x 6 cols (this group's jj parity), mask-free ----
    #pragma unroll
    for (int ii = 0; ii < 6; ++ii) {
        const int rb = (py + ii) * HLW + g * 13 + px;
        const float* t = tg + ii * 13;
        #pragma unroll
        for (int m = 0; m < 6; ++m) {
            const int cell = rb + m;
            const float4 xv = Ash4[cell];
            const uint4 v0 = ysh[cell];
            const uint4 v1 = ysh[NC + cell];
            const uint4 v2 = ysh[2 * NC + cell];

            // image-diff |x_q - x_p|^2, packed over (pc0,pc1)
            u64 d0 = add2(pack2(xv.x, xv.x), ng0);
            u64 d1 = add2(pack2(xv.y, xv.y), ng1);
            u64 d2 = add2(pack2(xv.z, xv.z), ng2);
            u64 sp = mul2(d0, d0); sp = ffma2(d1, d1, sp); sp = ffma2(d2, d2, sp);
            float s0, s1; unpack2(mul2(sp, cexp2), s0, s1);
            const float F0 = fmaf(0.9f, ex2(s0), 0.1f);
            const float F1 = fmaf(0.9f, ex2(s1), 0.1f);
            // TAB[ii][jj-5+6] for pc0, TAB[ii][jj-6+6] for pc1; jj = g+2m (g folded in tg)
            const float K0 = F0 * t[2 * m + 1];
            const float K1 = F1 * t[2 * m];
            acc1 += K0 + K1;

            // dots <y_c, y_q> in fp16x2 (12-deep chains)
            u32 dp0 = hmul2u(v0.x, yc0[0]);
            u32 dp1 = hmul2u(v0.x, yc1[0]);
            dp0 = hfma2u(v0.y, yc0[1], dp0);  dp1 = hfma2u(v0.y, yc1[1], dp1);
            dp0 = hfma2u(v0.z, yc0[2], dp0);  dp1 = hfma2u(v0.z, yc1[2], dp1);
            dp0 = hfma2u(v0.w, yc0[3], dp0);  dp1 = hfma2u(v0.w, yc1[3], dp1);
            dp0 = hfma2u(v1.x, yc0[4], dp0);  dp1 = hfma2u(v1.x, yc1[4], dp1);
            dp0 = hfma2u(v1.y, yc0[5], dp0);  dp1 = hfma2u(v1.y, yc1[5], dp1);
            dp0 = hfma2u(v1.z, yc0[6], dp0);  dp1 = hfma2u(v1.z, yc1[6], dp1);
            dp0 = hfma2u(v1.w, yc0[7], dp0);  dp1 = hfma2u(v1.w, yc1[7], dp1);
            dp0 = hfma2u(v2.x, yc0[8], dp0);  dp1 = hfma2u(v2.x, yc1[8], dp1);
            dp0 = hfma2u(v2.y, yc0[9], dp0);  dp1 = hfma2u(v2.y, yc1[9], dp1);
            dp0 = hfma2u(v2.z, yc0[10], dp0); dp1 = hfma2u(v2.z, yc1[10], dp1);
            dp0 = hfma2u(v2.w, yc0[11], dp0); dp1 = hfma2u(v2.w, yc1[11], dp1);

            accP0 = hfma2u(splat16(K0), dp0, accP0);
            accP1 = hfma2u(splat16(K1), dp1, accP1);
        }
    }

    // ---- epilogue ----
    float acc2;
    {
        __half2 a = *(__half2*)&accP0;
        __half2 b = *(__half2*)&accP1;
        acc2 = (__low2float(a) + __high2float(a)) + (__low2float(b) + __high2float(b));
    }
    if (g == 0) {
        // per-pixel corrections: subtract mask-free junk, add true OOB (full window, unhalved)
        const float CS5 = CS[5];
        const float SHt = CS5 * (1.0f + 2.0f * CS5) + CS5;
        const int h = th0 + py;
        const float csr = CS[min(5, 127 - h)];
        const int rv = min(5, 127 - h) + min(5, h) + 1;
        #pragma unroll
        for (int pc = 0; pc < 2; ++pc) {
            const int w = tw0 + 2 * px + pc;
            const float csw1 = CS[min(5, w)];
            const float csw2 = CS[min(5, 127 - w)];
            const float SHv = csr * (1.0f + csw1 + csw2) + csw2;
            const int cv = min(5, 127 - w) + min(5, w) + 1;
            const int noob = 121 - rv * cv;
            const float4 xc = pc ? xc1 : xc0;
            const float sx = xc.x * xc.x + xc.y * xc.y + xc.z * xc.z;
            const float F = fmaf(0.9f, ex2(sx * CEXP), 0.1f);
            acc1 += (float)noob * ex2((float)(h * h + w * w) * CXY) * F
                  - F * 2.0f * (SHt - SHv);
        }
    }

    // ---- block reduction + fused final reduction (deterministic) ----
    float part = acc1 - acc2;
    #pragma unroll
    for (int o = 16; o > 0; o >>= 1) part += __shfl_xor_sync(0xffffffffu, part, o);
    const int warp = tid >> 5, lane = tid & 31;
    if (lane == 0) red[warp] = part;
    __syncthreads();
    const int bid = ((bz * gridDim.y) + blockIdx.y) * gridDim.x + blockIdx.x;
    if (tid == 0) {
        float s = 0.f;
        #pragma unroll
        for (int wi = 0; wi < 8; ++wi) s += red[wi];
        g_part[bid] = s;
        __threadfence();
        unsigned old = atomicAdd(&g_cnt, 1u);
        lastflag = (old == NBLK - 1) ? 1 : 0;
    }
    __syncthreads();
    if (lastflag) {
        float v = g_part[tid];     // NBLK == NT == 256
        #pragma unroll
        for (int o = 16; o > 0; o >>= 1) v += __shfl_xor_sync(0xffffffffu, v, o);
        if (lane == 0) red[warp] = v;
        __syncthreads();
        if (tid == 0) {
            float s = 0.f;
            #pragma unroll
            for (int wi = 0; wi < 8; ++wi) s += red[wi];
            out[0] = s * (1.0f / 65536.0f);
            g_cnt = 0;
        }
    }
}

extern "C" void kernel_launch(void* const* d_in, const int* in_sizes, int n_in,
                              void* d_out, int out_size) {
    const float* x = (const float*)d_in[0];
    const float* y = (const float*)d_in[1];
    (void)in_sizes; (void)n_in; (void)out_size;
    dim3 grid(WW / TW, HH / TH, 4);
    crf_fused<<<grid, NT>>>(x, y, (float*)d_out);
}